// round 17
// baseline (speedup 1.0000x reference)
#include <cuda_runtime.h>

// Problem constants
#define Bn     32
#define Cn     40
#define Ln     16000
#define Kn     128
#define Sn     125      // LS / STRIDE
#define STILE  16       // s-values per block
#define NTILES 8        // 8*16 = 128 >= 125
#define CGRP   20       // channels per block
#define NCG    2        // channel groups
#define NOUT   (Bn * Cn * Sn)   // 160000 outputs (real part)

// ---- packed f32x2 helpers (Blackwell sm_103a) ----
#define FMA2(acc, a, b) \
    asm("fma.rn.f32x2 %0, %1, %2, %0;" : "+l"(acc) : "l"(a), "l"(b))
#define UNPACK2(lo, hi, in) \
    asm("mov.b64 {%0, %1}, %2;" : "=f"(lo), "=f"(hi) : "l"(in))

// ---------------- fast mode-0 kernel (real part only) ----------------
// Grid (8, 32, 2) = 512 blocks x 256 threads, __launch_bounds__(256, 4):
// 4 CTAs co-resident per SM (16K regs, 24.1KB smem each) -> prologues,
// barriers and drains of neighbours overlap each other's mainloops;
// 512 blocks ~ 3.5/SM = single wave.
//
//   block: cg -> channels [cg*20, cg*20+20), stile -> 16 s-values
//   warp w (8): g2 = w&1 -> 10-ch subgroup, q = w>>1 -> 32-tap K slice
//   lane:       sl = lane&15 -> s within tile, dd = lane>>4 -> 5-ch half
//   thread: 5 channels x 32 taps, FMA2 over natural tap pairs.
//
// x tile stored TAP-REVERSED: xs[sl][m] = x[(128*(s0+sl) - m) mod L] ->
// aligned dot product, zero packing. ks rows padded to 132 floats; the two
// in-warp kernel addresses (dd=0/1) differ by 5*132 floats (bank 20 apart)
// -> one wavefront. x phases conflict-free (banks 4*sl mod 32).
//
// smem (floats): ks 20*132=2640 | xs 16*132=2112 | part 4*20*16=1280
#define KSEG      132
#define XSEG      132
#define KS_FLOATS (CGRP * KSEG)          // 2640
#define XS_FLOATS (STILE * XSEG)         // 2112
#define PART_FLOATS (4 * CGRP * STILE)   // 1280
#define SMF_FAST  (KS_FLOATS + XS_FLOATS + PART_FLOATS)   // 6032 f = 24128 B

__global__ __launch_bounds__(256, 4)
void isac_conv_fast(const float* __restrict__ x,
                    const float* __restrict__ kr,
                    float* __restrict__ out)
{
    __shared__ float sm[SMF_FAST];
    float* ks   = sm;
    float* xs   = sm + KS_FLOATS;
    float* part = sm + KS_FLOATS + XS_FLOATS;

    const int tid   = threadIdx.x;
    const int stile = blockIdx.x;
    const int b     = blockIdx.y;
    const int cg    = blockIdx.z;                // channel group

    // ---- kernel copy into padded rows: ks[c*132+t] = kr[(cg*20+c)*128+t] ----
    const float* krg = kr + cg * CGRP * Kn;
    #pragma unroll
    for (int i = 0; i < 10; i++) {
        const int idx = tid + i * 256;           // idx < 2560
        ks[(idx >> 7) * KSEG + (idx & 127)] = krg[idx];
    }

    // ---- x tile, tap-reversed: xs[sl][m] = x[(128*(s0+sl) - m) mod L] ----
    const int base = stile * (STILE * Kn);       // 128*s0
    const float* xb = x + b * Ln;
    #pragma unroll
    for (int i = 0; i < 8; i++) {
        const int j  = tid + i * 256;            // j < 2048
        const int sl = j >> 7, m = j & 127;
        int g = base + sl * Kn - m;
        if (g < 0)        g += Ln;
        else if (g >= Ln) g -= Ln;
        xs[sl * XSEG + m] = xb[g];
    }
    __syncthreads();

    // ---- compute: 5 channels x 32-tap slice per thread ----
    const int lane = tid & 31;
    const int w    = tid >> 5;
    const int g2   = w & 1;                      // 10-channel subgroup
    const int q    = w >> 1;                     // 32-tap K slice
    const int sl   = lane & 15;                  // s within tile
    const int dd   = lane >> 4;                  // 5-channel half
    const int c0   = g2 * 10 + dd * 5;           // local channel base

    const ulonglong2* xp = (const ulonglong2*)(xs + sl * XSEG + q * 32);
    const float* kbase = ks + c0 * KSEG + q * 32;

    unsigned long long acc[5] = {0ull, 0ull, 0ull, 0ull, 0ull};

    #pragma unroll
    for (int i = 0; i < 8; i++) {                // 4 taps per iter
        const ulonglong2 xv = xp[i];
        #pragma unroll
        for (int j = 0; j < 5; j++) {
            const ulonglong2 kv =
                ((const ulonglong2*)(kbase + j * KSEG))[i];   // 2 addrs/warp
            FMA2(acc[j], xv.x, kv.x);
            FMA2(acc[j], xv.y, kv.y);
        }
    }

    // ---- fold even/odd tap sums, store scalar partials ----
    #pragma unroll
    for (int j = 0; j < 5; j++) {
        float lo, hi;
        UNPACK2(lo, hi, acc[j]);
        part[q * (CGRP * STILE) + (c0 + j) * STILE + sl] = lo + hi;
    }
    __syncthreads();

    // ---- reduce 4 K-slices, write (B, C, 125) float32 ----
    const int s0 = stile * STILE;
    #pragma unroll
    for (int i = 0; i < 2; i++) {
        const int idx = tid + i * 256;           // idx < 320
        if (idx < CGRP * STILE) {
            const int c = idx >> 4, s = idx & 15;
            const float v = part[idx]
                          + part[1 * CGRP * STILE + idx]
                          + part[2 * CGRP * STILE + idx]
                          + part[3 * CGRP * STILE + idx];
            if (s0 + s < Sn)
                out[(b * Cn + cg * CGRP + c) * Sn + (s0 + s)] = v;
        }
    }
}

// ---------------- fallback (full complex) — not expected to trigger ----------------
#define KERN_FLOATS (Cn * Kn)
#define FXSEG 132
#define SMEMB_FB ((2 * KERN_FLOATS + 32 * FXSEG) * 4)

__global__ __launch_bounds__(256)
void isac_conv_fallback(const float* __restrict__ x,
                        const float* __restrict__ kr,
                        const float* __restrict__ ki,
                        float* __restrict__ out,
                        int mode)   // 1 = planar, 2 = interleaved
{
    extern __shared__ float smem[];
    float* kr_s = smem;
    float* ki_s = smem + KERN_FLOATS;
    float* xs   = smem + 2 * KERN_FLOATS;

    const int tid = threadIdx.x, stile = blockIdx.x, b = blockIdx.y;
    #pragma unroll 4
    for (int idx = tid; idx < KERN_FLOATS; idx += 256) {
        const int c = idx >> 7, m = idx & 127;
        kr_s[idx] = kr[c * Kn + (127 - m)];
        ki_s[idx] = ki[c * Kn + (127 - m)];
    }
    const int gstart = stile * (32 * Kn) - 127;
    const float* xb = x + b * Ln;
    #pragma unroll 4
    for (int j = tid; j < 32 * Kn; j += 256) {
        int g = gstart + j;
        if (g < 0) g += Ln; else if (g >= Ln) g -= Ln;
        xs[(j >> 7) * FXSEG + (j & 127)] = xb[g];
    }
    __syncthreads();

    const int lane = tid & 31, w = tid >> 5;
    const int s = stile * 32 + lane, c0 = w * 5;
    const float4* xp  = (const float4*)(xs + lane * FXSEG);
    const float4* krp = (const float4*)(kr_s + c0 * Kn);
    const float4* kip = (const float4*)(ki_s + c0 * Kn);

    float ar[5] = {0,0,0,0,0}, ai[5] = {0,0,0,0,0};
    #pragma unroll 2
    for (int m4 = 0; m4 < Kn / 4; m4++) {
        const float4 xv = xp[m4];
        #pragma unroll
        for (int cc = 0; cc < 5; cc++) {
            const float4 kv = krp[cc * (Kn / 4) + m4];
            const float4 iv = kip[cc * (Kn / 4) + m4];
            ar[cc] = fmaf(xv.x, kv.x, fmaf(xv.y, kv.y, fmaf(xv.z, kv.z, fmaf(xv.w, kv.w, ar[cc]))));
            ai[cc] = fmaf(xv.x, iv.x, fmaf(xv.y, iv.y, fmaf(xv.z, iv.z, fmaf(xv.w, iv.w, ai[cc]))));
        }
    }
    if (s < Sn) {
        if (mode == 1) {
            #pragma unroll
            for (int cc = 0; cc < 5; cc++) {
                const int idx = (b * Cn + (c0 + cc)) * Sn + s;
                out[idx] = ar[cc]; out[NOUT + idx] = ai[cc];
            }
        } else {
            float2* o2 = (float2*)out;
            #pragma unroll
            for (int cc = 0; cc < 5; cc++)
                o2[(b * Cn + (c0 + cc)) * Sn + s] = make_float2(ar[cc], ai[cc]);
        }
    }
}

extern "C" void kernel_launch(void* const* d_in, const int* in_sizes, int n_in,
                              void* d_out, int out_size)
{
    const float* x  = (const float*)d_in[0];   // (32, 1, 16000) f32
    const float* kr = (const float*)d_in[1];   // (40, 128) f32
    const float* ki = (const float*)d_in[2];   // (40, 128) f32
    float* out = (float*)d_out;

    if (out_size == NOUT) {
        dim3 grid(NTILES, Bn, NCG);
        isac_conv_fast<<<grid, 256>>>(x, kr, out);
    } else {
        const int mode = (out_size == 2 * NOUT) ? 1 : 2;
        cudaFuncSetAttribute(isac_conv_fallback,
                             cudaFuncAttributeMaxDynamicSharedMemorySize, SMEMB_FB);
        dim3 grid(4, Bn);
        isac_conv_fallback<<<grid, 256, SMEMB_FB>>>(x, kr, ki, out, mode);
    }
}